// round 8
// baseline (speedup 1.0000x reference)
#include <cuda_runtime.h>
#include <cuda_fp16.h>

#define N_NODES 50000
#define E_EDGES 800000
#define D 128
#define NGRAPH 64

// ---------------- scratch (static __device__, no allocation) ----------------
__device__ __half g_h1[N_NODES * D];   // fp16 H buffers (gather operands)
__device__ __half g_h2[N_NODES * D];
__device__ float  g_x11[N_NODES * D];
__device__ float  g_x12[N_NODES * D];
__device__ float2 g_dc1[N_NODES];      // (weighted degree, count-as-float)
__device__ float2 g_dc2[N_NODES];
__device__ float  g_dis1[N_NODES];
__device__ float  g_dis2[N_NODES];
__device__ int    g_rp1[N_NODES + 1];
__device__ int    g_rp2[N_NODES + 1];
__device__ int    g_cur1[N_NODES];
__device__ int    g_cur2[N_NODES];
__device__ int2   g_m1[E_EDGES];       // (src, float_bits(norm))
__device__ int2   g_m2[E_EDGES];
__device__ float  g_sums[NGRAPH * D];
__device__ float  g_cnt[NGRAPH];

// ---------------- helpers ----------------
__device__ __forceinline__ void red_add_v4(float* p, float a, float b, float c, float d) {
    asm volatile(
        "{\n\t"
        ".reg .u64 q;\n\t"
        "cvta.to.global.u64 q, %0;\n\t"
        "red.global.add.v4.f32 [q], {%1, %2, %3, %4};\n\t"
        "}"
        :: "l"(p), "f"(a), "f"(b), "f"(c), "f"(d) : "memory");
}
__device__ __forceinline__ void red_add_v2(float2* p, float a, float b) {
    asm volatile(
        "{\n\t"
        ".reg .u64 q;\n\t"
        "cvta.to.global.u64 q, %0;\n\t"
        "red.global.add.v2.f32 [q], {%1, %2};\n\t"
        "}"
        :: "l"(p), "f"(a), "f"(b) : "memory");
}
__device__ __forceinline__ unsigned long long dup2(float x) {
    unsigned long long r;
    asm("mov.b64 %0, {%1, %1};" : "=l"(r) : "f"(x));
    return r;
}
__device__ __forceinline__ void fma2(unsigned long long& c, unsigned long long a,
                                     unsigned long long b) {
    asm("fma.rn.f32x2 %0, %1, %2, %0;" : "+l"(c) : "l"(a), "l"(b));
}

struct F8 { float4 a, b; };

// gather 8 fp16 channels (16B) of one H row -> fp32
__device__ __forceinline__ F8 ldg_h8(const __half* __restrict__ H, int row, int hl) {
    uint4 raw = __ldg((const uint4*)(H + row * 128 + hl * 8));
    __half2* p = reinterpret_cast<__half2*>(&raw);
    float2 f0 = __half22float2(p[0]);
    float2 f1 = __half22float2(p[1]);
    float2 f2 = __half22float2(p[2]);
    float2 f3 = __half22float2(p[3]);
    F8 r;
    r.a = make_float4(f0.x, f0.y, f1.x, f1.y);
    r.b = make_float4(f2.x, f2.y, f3.x, f3.y);
    return r;
}
__device__ __forceinline__ void fma8(F8& acc, float w, const F8& v) {
    acc.a.x = fmaf(w, v.a.x, acc.a.x); acc.a.y = fmaf(w, v.a.y, acc.a.y);
    acc.a.z = fmaf(w, v.a.z, acc.a.z); acc.a.w = fmaf(w, v.a.w, acc.a.w);
    acc.b.x = fmaf(w, v.b.x, acc.b.x); acc.b.y = fmaf(w, v.b.y, acc.b.y);
    acc.b.z = fmaf(w, v.b.z, acc.b.z); acc.b.w = fmaf(w, v.b.w, acc.b.w);
}

// ---------------- CSR build (both graphs per kernel) ----------------

__global__ void k_init() {
    int i = blockIdx.x * blockDim.x + threadIdx.x;
    if (i < N_NODES) {
        g_dc1[i] = make_float2(1.0f, 0.0f);   // self-loop weight 1
        g_dc2[i] = make_float2(1.0f, 0.0f);
    }
    if (i < NGRAPH * D) g_sums[i] = 0.0f;
    if (i < NGRAPH) g_cnt[i] = 0.0f;
}

__global__ void k_deg(const int* __restrict__ ei1, const float* __restrict__ ew1,
                      const int* __restrict__ ei2, const float* __restrict__ ew2) {
    int t = blockIdx.x * blockDim.x + threadIdx.x;
    if (t < E_EDGES) {
        red_add_v2(&g_dc1[ei1[E_EDGES + t]], ew1[t], 1.0f);
    } else if (t < 2 * E_EDGES) {
        int e = t - E_EDGES;
        red_add_v2(&g_dc2[ei2[E_EDGES + e]], ew2[e], 1.0f);
    }
}

__global__ __launch_bounds__(1024) void k_scan() {
    const int T = 1024;
    const int CH = (N_NODES + T - 1) / T;
    int g = blockIdx.x;
    const float2* dc = g ? g_dc2 : g_dc1;
    int* rp = g ? g_rp2 : g_rp1;
    int* cur = g ? g_cur2 : g_cur1;
    float* dis = g ? g_dis2 : g_dis1;
    __shared__ int sh[T];
    int t = threadIdx.x;
    int base = t * CH;
    int s = 0;
    for (int i = 0; i < CH; i++) {
        int idx = base + i;
        if (idx < N_NODES) s += (int)(dc[idx].y + 0.5f);
    }
    sh[t] = s;
    __syncthreads();
    for (int off = 1; off < T; off <<= 1) {
        int v = (t >= off) ? sh[t - off] : 0;
        __syncthreads();
        sh[t] += v;
        __syncthreads();
    }
    int run = (t == 0) ? 0 : sh[t - 1];
    for (int i = 0; i < CH; i++) {
        int idx = base + i;
        if (idx < N_NODES) {
            rp[idx] = run;
            cur[idx] = run;
            run += (int)(dc[idx].y + 0.5f);
            dis[idx] = rsqrtf(dc[idx].x);
        }
    }
    if (t == T - 1) rp[N_NODES] = run;
}

__global__ void k_fill(const int* __restrict__ ei1, const float* __restrict__ ew1,
                       const int* __restrict__ ei2, const float* __restrict__ ew2) {
    int t = blockIdx.x * blockDim.x + threadIdx.x;
    if (t < E_EDGES) {
        int s = ei1[t], d = ei1[E_EDGES + t];
        float norm = g_dis1[s] * ew1[t] * g_dis1[d];
        int pos = atomicAdd(&g_cur1[d], 1);
        g_m1[pos] = make_int2(s, __float_as_int(norm));
    } else if (t < 2 * E_EDGES) {
        int e = t - E_EDGES;
        int s = ei2[e], d = ei2[E_EDGES + e];
        float norm = g_dis2[s] * ew2[e] * g_dis2[d];
        int pos = atomicAdd(&g_cur2[d], 1);
        g_m2[pos] = make_int2(s, __float_as_int(norm));
    }
}

// ---------------- GEMM: C[N,128](fp16) = A[N,128](fp32) @ W[128,128] ----------
__global__ __launch_bounds__(256) void k_gemm1m(
    const float* __restrict__ A, const float* __restrict__ W, __half* __restrict__ C) {
    __shared__ __align__(16) float As[16][132];
    __shared__ __align__(16) float Ws[16][128];

    int row0 = blockIdx.x * 128;
    int t = threadIdx.x;
    int tx = t & 15;
    int ty = t >> 4;

    unsigned long long acc2[4][8];
#pragma unroll
    for (int i = 0; i < 4; i++)
#pragma unroll
        for (int j = 0; j < 8; j++) acc2[i][j] = 0ull;

    for (int kk = 0; kk < 128; kk += 16) {
#pragma unroll
        for (int i = 0; i < 2; i++) {
            int f4 = t * 2 + i;
            int r = f4 >> 2;
            int q = f4 & 3;
            int grow = row0 + r;
            float4 v = make_float4(0.f, 0.f, 0.f, 0.f);
            if (grow < N_NODES)
                v = *(const float4*)(A + grow * 128 + kk + q * 4);
            As[q * 4 + 0][r] = v.x;
            As[q * 4 + 1][r] = v.y;
            As[q * 4 + 2][r] = v.z;
            As[q * 4 + 3][r] = v.w;
        }
#pragma unroll
        for (int i = 0; i < 2; i++) {
            int f4 = t * 2 + i;
            int r = f4 >> 5;
            int c = (f4 & 31) * 4;
            *(float4*)&Ws[r][c] = *(const float4*)(W + (kk + r) * 128 + c);
        }
        __syncthreads();

#pragma unroll
        for (int k = 0; k < 16; k++) {
            ulonglong2 av0 = *(const ulonglong2*)&As[k][ty * 8];
            ulonglong2 av1 = *(const ulonglong2*)&As[k][ty * 8 + 4];
            unsigned long long ap[4] = {av0.x, av0.y, av1.x, av1.y};
            float4 b0 = *(const float4*)&Ws[k][tx * 8];
            float4 b1 = *(const float4*)&Ws[k][tx * 8 + 4];
            unsigned long long bd[8];
            bd[0] = dup2(b0.x); bd[1] = dup2(b0.y); bd[2] = dup2(b0.z); bd[3] = dup2(b0.w);
            bd[4] = dup2(b1.x); bd[5] = dup2(b1.y); bd[6] = dup2(b1.z); bd[7] = dup2(b1.w);
#pragma unroll
            for (int i = 0; i < 4; i++)
#pragma unroll
                for (int j = 0; j < 8; j++) fma2(acc2[i][j], ap[i], bd[j]);
        }
        __syncthreads();
    }

#pragma unroll
    for (int i2 = 0; i2 < 4; i2++) {
        float2 f[8];
#pragma unroll
        for (int j = 0; j < 8; j++) f[j] = *(float2*)&acc2[i2][j];
#pragma unroll
        for (int rs = 0; rs < 2; rs++) {
            int r = row0 + ty * 8 + i2 * 2 + rs;
            if (r < N_NODES) {
                float v0 = rs ? f[0].y : f[0].x, v1 = rs ? f[1].y : f[1].x;
                float v2 = rs ? f[2].y : f[2].x, v3 = rs ? f[3].y : f[3].x;
                float v4 = rs ? f[4].y : f[4].x, v5 = rs ? f[5].y : f[5].x;
                float v6 = rs ? f[6].y : f[6].x, v7 = rs ? f[7].y : f[7].x;
                __align__(16) __half2 hh[4];
                hh[0] = __floats2half2_rn(v0, v1);
                hh[1] = __floats2half2_rn(v2, v3);
                hh[2] = __floats2half2_rn(v4, v5);
                hh[3] = __floats2half2_rn(v6, v7);
                *(uint4*)(C + r * 128 + tx * 8) = *(uint4*)hh;
            }
        }
    }
}

// ------------- aggregation: half-warp per edge, 8 channels per lane -----------
// Lane layout: hl = lane&15 owns channels [hl*8, hl*8+8); half = lane>>4 picks
// which of two concurrent edges this lane gathers. Zero-padded meta makes the
// odd tail branch-free (w=0 gathers of row 0 add nothing).
__device__ __forceinline__ F8 agg_node8(
    const __half* __restrict__ H, const int* __restrict__ rp,
    const int2* __restrict__ meta, const float* __restrict__ dis,
    int d, int lane, const float* __restrict__ bias) {
    int hl = lane & 15;
    int half = lane >> 4;
    int beg = rp[d], end = rp[d + 1];

    F8 acc;
    acc.a = make_float4(0.f, 0.f, 0.f, 0.f);
    acc.b = make_float4(0.f, 0.f, 0.f, 0.f);
    if (half == 0) {   // self-loop + bias only once
        float n2 = dis[d]; n2 *= n2;
        F8 hd = ldg_h8(H, d, hl);
        float4 bv0 = *(const float4*)(bias + hl * 8);
        float4 bv1 = *(const float4*)(bias + hl * 8 + 4);
        acc.a = make_float4(fmaf(n2, hd.a.x, bv0.x), fmaf(n2, hd.a.y, bv0.y),
                            fmaf(n2, hd.a.z, bv0.z), fmaf(n2, hd.a.w, bv0.w));
        acc.b = make_float4(fmaf(n2, hd.b.x, bv1.x), fmaf(n2, hd.b.y, bv1.y),
                            fmaf(n2, hd.b.z, bv1.z), fmaf(n2, hd.b.w, bv1.w));
    }

    for (int base = beg; base < end; base += 32) {
        int2 mm = make_int2(0, 0);
        if (base + lane < end) mm = __ldg(&meta[base + lane]);
        int m = min(32, end - base);
        int j = 0;
        for (; j + 8 <= m; j += 8) {   // 8 edges per burst, 4 loads per lane
            int ss[4]; float ww[4];
#pragma unroll
            for (int u = 0; u < 4; u++) {
                int e = j + 2 * u + half;
                ss[u] = __shfl_sync(0xffffffffu, mm.x, e);
                ww[u] = __int_as_float(__shfl_sync(0xffffffffu, mm.y, e));
            }
            F8 vv[4];
#pragma unroll
            for (int u = 0; u < 4; u++) vv[u] = ldg_h8(H, ss[u], hl);
#pragma unroll
            for (int u = 0; u < 4; u++) fma8(acc, ww[u], vv[u]);
        }
        for (; j < m; j += 2) {        // 2 edges per step (tail pad has w=0)
            int e = j + half;
            int s = __shfl_sync(0xffffffffu, mm.x, e);
            float w = __int_as_float(__shfl_sync(0xffffffffu, mm.y, e));
            F8 v = ldg_h8(H, s, hl);
            fma8(acc, w, v);
        }
    }

    // combine the two half-warps' partial sums (same channels at lane, lane^16)
    acc.a.x += __shfl_xor_sync(0xffffffffu, acc.a.x, 16);
    acc.a.y += __shfl_xor_sync(0xffffffffu, acc.a.y, 16);
    acc.a.z += __shfl_xor_sync(0xffffffffu, acc.a.z, 16);
    acc.a.w += __shfl_xor_sync(0xffffffffu, acc.a.w, 16);
    acc.b.x += __shfl_xor_sync(0xffffffffu, acc.b.x, 16);
    acc.b.y += __shfl_xor_sync(0xffffffffu, acc.b.y, 16);
    acc.b.z += __shfl_xor_sync(0xffffffffu, acc.b.z, 16);
    acc.b.w += __shfl_xor_sync(0xffffffffu, acc.b.w, 16);
    return acc;
}

// layer-1 aggregation, one graph, warp per node
__global__ __launch_bounds__(256) void k_agg1g(
    const __half* __restrict__ H, float* __restrict__ X,
    const float* __restrict__ bias,
    const int* __restrict__ rp, const int2* __restrict__ meta,
    const float* __restrict__ dis) {
    int d = (blockIdx.x * blockDim.x + threadIdx.x) >> 5;
    int lane = threadIdx.x & 31;
    if (d >= N_NODES) return;
    F8 acc = agg_node8(H, rp, meta, dis, d, lane, bias);
    if ((lane >> 4) == 0) {
        int hl = lane & 15;
        *(float4*)(X + d * 128 + hl * 8) = acc.a;
        *(float4*)(X + d * 128 + hl * 8 + 4) = acc.b;
    }
}

// layer-2 aggregation fused with pooling (both graphs)
__global__ __launch_bounds__(256) void k_agg2(
    const __half* __restrict__ H1, const __half* __restrict__ H2,
    const float* __restrict__ bias, const int* __restrict__ batch) {
    int d = (blockIdx.x * blockDim.x + threadIdx.x) >> 5;
    int lane = threadIdx.x & 31;
    if (d >= N_NODES) return;
    F8 a21 = agg_node8(H1, g_rp1, g_m1, g_dis1, d, lane, bias);
    F8 a22 = agg_node8(H2, g_rp2, g_m2, g_dis2, d, lane, bias);

    if ((lane >> 4) == 0) {
        int hl = lane & 15;
        int off = d * 128 + hl * 8;
        float4 a11a = *(const float4*)(g_x11 + off);
        float4 a11b = *(const float4*)(g_x11 + off + 4);
        float4 a12a = *(const float4*)(g_x12 + off);
        float4 a12b = *(const float4*)(g_x12 + off + 4);
        float p0 = (a12a.x - a11a.x) * (a22.a.x - a21.a.x);
        float p1 = (a12a.y - a11a.y) * (a22.a.y - a21.a.y);
        float p2 = (a12a.z - a11a.z) * (a22.a.z - a21.a.z);
        float p3 = (a12a.w - a11a.w) * (a22.a.w - a21.a.w);
        float p4 = (a12b.x - a11b.x) * (a22.b.x - a21.b.x);
        float p5 = (a12b.y - a11b.y) * (a22.b.y - a21.b.y);
        float p6 = (a12b.z - a11b.z) * (a22.b.z - a21.b.z);
        float p7 = (a12b.w - a11b.w) * (a22.b.w - a21.b.w);
        int gph = batch[d];
        red_add_v4(g_sums + gph * 128 + hl * 8, p0, p1, p2, p3);
        red_add_v4(g_sums + gph * 128 + hl * 8 + 4, p4, p5, p6, p7);
        if (lane == 0) atomicAdd(&g_cnt[gph], 1.0f);
    }
}

// ---------------- final MLP ----------------
__global__ __launch_bounds__(128) void k_mlp(
    const float* __restrict__ M1w, const float* __restrict__ M1b,
    const float* __restrict__ M2w, const float* __restrict__ M2b,
    const float* __restrict__ M3w, const float* __restrict__ M3b,
    const float* __restrict__ M4w, const float* __restrict__ M4b,
    float* __restrict__ out) {
    __shared__ float gv[128], h1s[128], h2s[64], h3s[32];
    int g = blockIdx.x;
    int t = threadIdx.x;
    float cnt = fmaxf(g_cnt[g], 1.0f);
    gv[t] = g_sums[g * 128 + t] / cnt;
    __syncthreads();
    float acc = M1b[t];
#pragma unroll 8
    for (int c = 0; c < 128; c++) acc += gv[c] * M1w[c * 128 + t];
    h1s[t] = acc;
    __syncthreads();
    if (t < 64) {
        acc = M2b[t];
#pragma unroll 8
        for (int c = 0; c < 128; c++) acc += h1s[c] * M2w[c * 64 + t];
        h2s[t] = acc;
    }
    __syncthreads();
    if (t < 32) {
        acc = M3b[t];
#pragma unroll 8
        for (int c = 0; c < 64; c++) acc += h2s[c] * M3w[c * 32 + t];
        h3s[t] = acc;
    }
    __syncthreads();
    if (t < 32) {
        float v = h3s[t] * M4w[t];
#pragma unroll
        for (int off = 16; off > 0; off >>= 1)
            v += __shfl_down_sync(0xffffffff, v, off);
        if (t == 0) out[g] = v + M4b[0];
    }
}

// ---------------- launch (R3/R6/R7 topology) ----------------
extern "C" void kernel_launch(void* const* d_in, const int* in_sizes, int n_in,
                              void* d_out, int out_size) {
    const int*   ei1  = (const int*)d_in[0];
    const float* ew1  = (const float*)d_in[1];
    const int*   ei2  = (const int*)d_in[2];
    const float* ew2  = (const float*)d_in[3];
    const float* fm0  = (const float*)d_in[4];
    const float* fm1  = (const float*)d_in[5];
    const int*   batch = (const int*)d_in[6];
    const float* W1  = (const float*)d_in[7];
    const float* b1  = (const float*)d_in[8];
    const float* W2  = (const float*)d_in[9];
    const float* b2  = (const float*)d_in[10];
    const float* M1w = (const float*)d_in[11];
    const float* M1b = (const float*)d_in[12];
    const float* M2w = (const float*)d_in[13];
    const float* M2b = (const float*)d_in[14];
    const float* M3w = (const float*)d_in[15];
    const float* M3b = (const float*)d_in[16];
    const float* M4w = (const float*)d_in[17];
    const float* M4b = (const float*)d_in[18];
    float* out = (float*)d_out;

    void *p_h1, *p_h2, *p_x11, *p_x12;
    void *p_rp1, *p_rp2, *p_m1, *p_m2, *p_dis1, *p_dis2;
    cudaGetSymbolAddress(&p_h1, g_h1);
    cudaGetSymbolAddress(&p_h2, g_h2);
    cudaGetSymbolAddress(&p_x11, g_x11);
    cudaGetSymbolAddress(&p_x12, g_x12);
    cudaGetSymbolAddress(&p_rp1, g_rp1);
    cudaGetSymbolAddress(&p_rp2, g_rp2);
    cudaGetSymbolAddress(&p_m1, g_m1);
    cudaGetSymbolAddress(&p_m2, g_m2);
    cudaGetSymbolAddress(&p_dis1, g_dis1);
    cudaGetSymbolAddress(&p_dis2, g_dis2);
    __half* h1 = (__half*)p_h1;  __half* h2 = (__half*)p_h2;
    float* x11 = (float*)p_x11;  float* x12 = (float*)p_x12;

    static cudaStream_t sA = nullptr, sB = nullptr;
    static cudaEvent_t eF = nullptr, eCSR = nullptr, eA = nullptr, eB = nullptr;
    if (sA == nullptr) {
        cudaStreamCreateWithFlags(&sA, cudaStreamNonBlocking);
        cudaStreamCreateWithFlags(&sB, cudaStreamNonBlocking);
        cudaEventCreateWithFlags(&eF, cudaEventDisableTiming);
        cudaEventCreateWithFlags(&eCSR, cudaEventDisableTiming);
        cudaEventCreateWithFlags(&eA, cudaEventDisableTiming);
        cudaEventCreateWithFlags(&eB, cudaEventDisableTiming);
    }

    const int TPB = 256;
    int nodeBlocks = (N_NODES + TPB - 1) / TPB;
    int edgeBlocks = (2 * E_EDGES + TPB - 1) / TPB;
    int gemmBlocks = (N_NODES + 127) / 128;
    int aggBlocks  = (N_NODES * 32 + TPB - 1) / TPB;

    // fork: per-graph gemm1 chains run concurrently with CSR build
    cudaEventRecord(eF, 0);
    cudaStreamWaitEvent(sA, eF, 0);
    cudaStreamWaitEvent(sB, eF, 0);
    k_gemm1m<<<gemmBlocks, TPB, 0, sA>>>(fm0, W1, h1);
    k_gemm1m<<<gemmBlocks, TPB, 0, sB>>>(fm1, W1, h2);

    // CSR build chain on default stream (completes before any agg starts)
    k_init<<<nodeBlocks, TPB>>>();
    k_deg<<<edgeBlocks, TPB>>>(ei1, ew1, ei2, ew2);
    k_scan<<<2, 1024>>>();
    k_fill<<<edgeBlocks, TPB>>>(ei1, ew1, ei2, ew2);
    cudaEventRecord(eCSR, 0);
    cudaStreamWaitEvent(sA, eCSR, 0);
    cudaStreamWaitEvent(sB, eCSR, 0);

    // per-graph: agg1 then gemm2
    k_agg1g<<<aggBlocks, TPB, 0, sA>>>(h1, x11, b1, (const int*)p_rp1,
                                       (const int2*)p_m1, (const float*)p_dis1);
    k_gemm1m<<<gemmBlocks, TPB, 0, sA>>>(x11, W2, h1);
    k_agg1g<<<aggBlocks, TPB, 0, sB>>>(h2, x12, b1, (const int*)p_rp2,
                                       (const int2*)p_m2, (const float*)p_dis2);
    k_gemm1m<<<gemmBlocks, TPB, 0, sB>>>(x12, W2, h2);

    cudaEventRecord(eA, sA);
    cudaEventRecord(eB, sB);
    cudaStreamWaitEvent(0, eA, 0);
    cudaStreamWaitEvent(0, eB, 0);

    // join: layer-2 aggregation fused with pooling, then MLP
    k_agg2<<<aggBlocks, TPB>>>(h1, h2, b2, batch);
    k_mlp<<<NGRAPH, 128>>>(M1w, M1b, M2w, M2b, M3w, M3b, M4w, M4b, out);
}

// round 9
// speedup vs baseline: 1.4053x; 1.4053x over previous
#include <cuda_runtime.h>
#include <cuda_fp16.h>
#include <cstdint>

#define N_NODES 50000
#define E_EDGES 800000
#define D 128
#define NGRAPH 64

// ---------------- scratch (static __device__, no allocation) ----------------
__device__ __half g_h1[N_NODES * D];   // fp16 H buffers (gather operands)
__device__ __half g_h2[N_NODES * D];
__device__ float  g_x11[N_NODES * D];
__device__ float  g_x12[N_NODES * D];
__device__ float2 g_dc1[N_NODES];      // (weighted degree, count-as-float)
__device__ float2 g_dc2[N_NODES];
__device__ float  g_dis1[N_NODES];
__device__ float  g_dis2[N_NODES];
__device__ int    g_rp1[N_NODES + 1];
__device__ int    g_rp2[N_NODES + 1];
__device__ int    g_cur1[N_NODES];
__device__ int    g_cur2[N_NODES];
__device__ int2   g_m1[E_EDGES];       // (src, float_bits(norm))
__device__ int2   g_m2[E_EDGES];
__device__ float  g_sums[NGRAPH * D];
__device__ float  g_cnt[NGRAPH];

// ---------------- helpers ----------------
__device__ __forceinline__ void red_add_v4(float* p, float a, float b, float c, float d) {
    asm volatile(
        "{\n\t"
        ".reg .u64 q;\n\t"
        "cvta.to.global.u64 q, %0;\n\t"
        "red.global.add.v4.f32 [q], {%1, %2, %3, %4};\n\t"
        "}"
        :: "l"(p), "f"(a), "f"(b), "f"(c), "f"(d) : "memory");
}
__device__ __forceinline__ void red_add_v2(float2* p, float a, float b) {
    asm volatile(
        "{\n\t"
        ".reg .u64 q;\n\t"
        "cvta.to.global.u64 q, %0;\n\t"
        "red.global.add.v2.f32 [q], {%1, %2};\n\t"
        "}"
        :: "l"(p), "f"(a), "f"(b) : "memory");
}
// gather 4 fp16 channels of one H row -> fp32
__device__ __forceinline__ float4 ldg_h4(const __half* __restrict__ H, int row, int lane) {
    uint2 raw = __ldg((const uint2*)(H + row * 128 + lane * 4));
    __half2 p0 = *reinterpret_cast<__half2*>(&raw.x);
    __half2 p1 = *reinterpret_cast<__half2*>(&raw.y);
    float2 f0 = __half22float2(p0);
    float2 f1 = __half22float2(p1);
    return make_float4(f0.x, f0.y, f1.x, f1.y);
}

// ---------------- CSR build (both graphs per kernel) ----------------

__global__ void k_init() {
    int i = blockIdx.x * blockDim.x + threadIdx.x;
    if (i < N_NODES) {
        g_dc1[i] = make_float2(1.0f, 0.0f);   // self-loop weight 1
        g_dc2[i] = make_float2(1.0f, 0.0f);
    }
    if (i < NGRAPH * D) g_sums[i] = 0.0f;
    if (i < NGRAPH) g_cnt[i] = 0.0f;
}

__global__ void k_deg(const int* __restrict__ ei1, const float* __restrict__ ew1,
                      const int* __restrict__ ei2, const float* __restrict__ ew2) {
    int t = blockIdx.x * blockDim.x + threadIdx.x;
    if (t < E_EDGES) {
        red_add_v2(&g_dc1[ei1[E_EDGES + t]], ew1[t], 1.0f);
    } else if (t < 2 * E_EDGES) {
        int e = t - E_EDGES;
        red_add_v2(&g_dc2[ei2[E_EDGES + e]], ew2[e], 1.0f);
    }
}

__global__ __launch_bounds__(1024) void k_scan() {
    const int T = 1024;
    const int CH = (N_NODES + T - 1) / T;
    int g = blockIdx.x;
    const float2* dc = g ? g_dc2 : g_dc1;
    int* rp = g ? g_rp2 : g_rp1;
    int* cur = g ? g_cur2 : g_cur1;
    float* dis = g ? g_dis2 : g_dis1;
    __shared__ int sh[T];
    int t = threadIdx.x;
    int base = t * CH;
    int s = 0;
    for (int i = 0; i < CH; i++) {
        int idx = base + i;
        if (idx < N_NODES) s += (int)(dc[idx].y + 0.5f);
    }
    sh[t] = s;
    __syncthreads();
    for (int off = 1; off < T; off <<= 1) {
        int v = (t >= off) ? sh[t - off] : 0;
        __syncthreads();
        sh[t] += v;
        __syncthreads();
    }
    int run = (t == 0) ? 0 : sh[t - 1];
    for (int i = 0; i < CH; i++) {
        int idx = base + i;
        if (idx < N_NODES) {
            rp[idx] = run;
            cur[idx] = run;
            run += (int)(dc[idx].y + 0.5f);
            dis[idx] = rsqrtf(dc[idx].x);
        }
    }
    if (t == T - 1) rp[N_NODES] = run;
}

__global__ void k_fill(const int* __restrict__ ei1, const float* __restrict__ ew1,
                       const int* __restrict__ ei2, const float* __restrict__ ew2) {
    int t = blockIdx.x * blockDim.x + threadIdx.x;
    if (t < E_EDGES) {
        int s = ei1[t], d = ei1[E_EDGES + t];
        float norm = g_dis1[s] * ew1[t] * g_dis1[d];
        int pos = atomicAdd(&g_cur1[d], 1);
        g_m1[pos] = make_int2(s, __float_as_int(norm));
    } else if (t < 2 * E_EDGES) {
        int e = t - E_EDGES;
        int s = ei2[e], d = ei2[E_EDGES + e];
        float norm = g_dis2[s] * ew2[e] * g_dis2[d];
        int pos = atomicAdd(&g_cur2[d], 1);
        g_m2[pos] = make_int2(s, __float_as_int(norm));
    }
}

// -------- tensor-core GEMM: C[N,128](fp16) = A[N,128](fp32) @ W[128,128] ------
// mma.sync.m16n8k16 f16*f16 + f32. W transposed to fp16 smem (Wt[n][k], padded);
// A fragments loaded from global fp32 and converted in-register.
__global__ __launch_bounds__(256) void k_gemm_tc(
    const float* __restrict__ A, const float* __restrict__ W, __half* __restrict__ C) {
    __shared__ __half Wt[128][136];   // [n][k], pad 8 halves -> conflict-free B frags

    int t = threadIdx.x;
    for (int i = t; i < 128 * 128; i += 256) {
        int k = i >> 7, n = i & 127;
        Wt[n][k] = __float2half_rn(W[i]);
    }
    __syncthreads();

    int w = t >> 5;          // warp 0..7 -> 16-row strip
    int lane = t & 31;
    int g = lane >> 2;       // group (0..7)
    int tq = lane & 3;       // thread-in-group
    int r0 = blockIdx.x * 128 + w * 16 + g;
    int r1 = r0 + 8;
    bool ok0 = r0 < N_NODES, ok1 = r1 < N_NODES;

    // preload A fragments for all 8 k-steps (a0..a3 per PTX m16n8k16 layout)
    uint32_t af[8][4];
#pragma unroll
    for (int ks = 0; ks < 8; ks++) {
        int c = ks * 16 + tq * 2;
        float2 z = make_float2(0.f, 0.f);
        float2 f0 = ok0 ? *(const float2*)(A + r0 * 128 + c) : z;       // (r,  c)
        float2 f1 = ok1 ? *(const float2*)(A + r1 * 128 + c) : z;       // (r+8,c)
        float2 f2 = ok0 ? *(const float2*)(A + r0 * 128 + c + 8) : z;   // (r,  c+8)
        float2 f3 = ok1 ? *(const float2*)(A + r1 * 128 + c + 8) : z;   // (r+8,c+8)
        __half2 h0 = __floats2half2_rn(f0.x, f0.y);
        __half2 h1 = __floats2half2_rn(f1.x, f1.y);
        __half2 h2 = __floats2half2_rn(f2.x, f2.y);
        __half2 h3 = __floats2half2_rn(f3.x, f3.y);
        af[ks][0] = *reinterpret_cast<uint32_t*>(&h0);
        af[ks][1] = *reinterpret_cast<uint32_t*>(&h1);
        af[ks][2] = *reinterpret_cast<uint32_t*>(&h2);
        af[ks][3] = *reinterpret_cast<uint32_t*>(&h3);
    }

    int n = 0;               // B/C column group base handled per n-tile
#pragma unroll
    for (int nt = 0; nt < 16; nt++) {
        float c0 = 0.f, c1 = 0.f, c2 = 0.f, c3 = 0.f;
        n = nt * 8 + g;
        const __half* wrow = &Wt[n][0];
#pragma unroll
        for (int ks = 0; ks < 8; ks++) {
            uint32_t b0 = *(const uint32_t*)(wrow + ks * 16 + tq * 2);       // k=2tq,2tq+1
            uint32_t b1 = *(const uint32_t*)(wrow + ks * 16 + tq * 2 + 8);   // +8
            asm volatile(
                "mma.sync.aligned.m16n8k16.row.col.f32.f16.f16.f32 "
                "{%0,%1,%2,%3}, {%4,%5,%6,%7}, {%8,%9}, {%0,%1,%2,%3};\n"
                : "+f"(c0), "+f"(c1), "+f"(c2), "+f"(c3)
                : "r"(af[ks][0]), "r"(af[ks][1]), "r"(af[ks][2]), "r"(af[ks][3]),
                  "r"(b0), "r"(b1));
        }
        // C layout: (c0,c1)=row g, cols 2tq,2tq+1; (c2,c3)=row g+8
        int col = nt * 8 + tq * 2;
        if (ok0) {
            __half2 h = __floats2half2_rn(c0, c1);
            *(uint32_t*)(C + r0 * 128 + col) = *reinterpret_cast<uint32_t*>(&h);
        }
        if (ok1) {
            __half2 h = __floats2half2_rn(c2, c3);
            *(uint32_t*)(C + r1 * 128 + col) = *reinterpret_cast<uint32_t*>(&h);
        }
    }
}

// ---------------- aggregation body (fp16 gathers, fp32 accumulate) ------------
__device__ __forceinline__ float4 agg_node(
    const __half* __restrict__ H, const int* __restrict__ rp,
    const int2* __restrict__ meta, const float* __restrict__ dis,
    int d, int lane, float4 bv) {
    int beg = rp[d], end = rp[d + 1];
    float n2 = dis[d]; n2 *= n2;
    float4 hd = ldg_h4(H, d, lane);
    float4 acc = make_float4(fmaf(n2, hd.x, bv.x), fmaf(n2, hd.y, bv.y),
                             fmaf(n2, hd.z, bv.z), fmaf(n2, hd.w, bv.w));

    for (int base = beg; base < end; base += 32) {
        int2 mm = make_int2(0, 0);
        if (base + lane < end) mm = __ldg(&meta[base + lane]);
        int m = min(32, end - base);
        int j = 0;
        for (; j + 4 <= m; j += 4) {
            int s0 = __shfl_sync(0xffffffffu, mm.x, j);
            int s1 = __shfl_sync(0xffffffffu, mm.x, j + 1);
            int s2 = __shfl_sync(0xffffffffu, mm.x, j + 2);
            int s3 = __shfl_sync(0xffffffffu, mm.x, j + 3);
            float w0 = __int_as_float(__shfl_sync(0xffffffffu, mm.y, j));
            float w1 = __int_as_float(__shfl_sync(0xffffffffu, mm.y, j + 1));
            float w2 = __int_as_float(__shfl_sync(0xffffffffu, mm.y, j + 2));
            float w3 = __int_as_float(__shfl_sync(0xffffffffu, mm.y, j + 3));
            float4 v0 = ldg_h4(H, s0, lane);
            float4 v1 = ldg_h4(H, s1, lane);
            float4 v2 = ldg_h4(H, s2, lane);
            float4 v3 = ldg_h4(H, s3, lane);
            acc.x = fmaf(w0, v0.x, fmaf(w1, v1.x, fmaf(w2, v2.x, fmaf(w3, v3.x, acc.x))));
            acc.y = fmaf(w0, v0.y, fmaf(w1, v1.y, fmaf(w2, v2.y, fmaf(w3, v3.y, acc.y))));
            acc.z = fmaf(w0, v0.z, fmaf(w1, v1.z, fmaf(w2, v2.z, fmaf(w3, v3.z, acc.z))));
            acc.w = fmaf(w0, v0.w, fmaf(w1, v1.w, fmaf(w2, v2.w, fmaf(w3, v3.w, acc.w))));
        }
        for (; j < m; j++) {
            int s = __shfl_sync(0xffffffffu, mm.x, j);
            float w = __int_as_float(__shfl_sync(0xffffffffu, mm.y, j));
            float4 v = ldg_h4(H, s, lane);
            acc.x = fmaf(w, v.x, acc.x); acc.y = fmaf(w, v.y, acc.y);
            acc.z = fmaf(w, v.z, acc.z); acc.w = fmaf(w, v.w, acc.w);
        }
    }
    return acc;
}

// layer-1 aggregation, one graph, warp per node
__global__ __launch_bounds__(256) void k_agg1g(
    const __half* __restrict__ H, float* __restrict__ X,
    const float* __restrict__ bias,
    const int* __restrict__ rp, const int2* __restrict__ meta,
    const float* __restrict__ dis) {
    int d = (blockIdx.x * blockDim.x + threadIdx.x) >> 5;
    int lane = threadIdx.x & 31;
    if (d >= N_NODES) return;
    float4 bv = *(const float4*)(bias + lane * 4);
    float4 acc = agg_node(H, rp, meta, dis, d, lane, bv);
    *(float4*)(X + d * 128 + lane * 4) = acc;
}

// layer-2 aggregation fused with pooling (both graphs)
__global__ __launch_bounds__(256) void k_agg2(
    const __half* __restrict__ H1, const __half* __restrict__ H2,
    const float* __restrict__ bias, const int* __restrict__ batch) {
    int d = (blockIdx.x * blockDim.x + threadIdx.x) >> 5;
    int lane = threadIdx.x & 31;
    if (d >= N_NODES) return;
    float4 bv = *(const float4*)(bias + lane * 4);
    float4 a21 = agg_node(H1, g_rp1, g_m1, g_dis1, d, lane, bv);
    float4 a22 = agg_node(H2, g_rp2, g_m2, g_dis2, d, lane, bv);

    int off = d * 128 + lane * 4;
    float4 a11 = *(const float4*)(g_x11 + off);
    float4 a12 = *(const float4*)(g_x12 + off);
    float px = (a12.x - a11.x) * (a22.x - a21.x);
    float py = (a12.y - a11.y) * (a22.y - a21.y);
    float pz = (a12.z - a11.z) * (a22.z - a21.z);
    float pw = (a12.w - a11.w) * (a22.w - a21.w);
    int gph = batch[d];
    red_add_v4(g_sums + gph * 128 + lane * 4, px, py, pz, pw);
    if (lane == 0) atomicAdd(&g_cnt[gph], 1.0f);
}

// ---------------- final MLP ----------------
__global__ __launch_bounds__(128) void k_mlp(
    const float* __restrict__ M1w, const float* __restrict__ M1b,
    const float* __restrict__ M2w, const float* __restrict__ M2b,
    const float* __restrict__ M3w, const float* __restrict__ M3b,
    const float* __restrict__ M4w, const float* __restrict__ M4b,
    float* __restrict__ out) {
    __shared__ float gv[128], h1s[128], h2s[64], h3s[32];
    int g = blockIdx.x;
    int t = threadIdx.x;
    float cnt = fmaxf(g_cnt[g], 1.0f);
    gv[t] = g_sums[g * 128 + t] / cnt;
    __syncthreads();
    float acc = M1b[t];
#pragma unroll 8
    for (int c = 0; c < 128; c++) acc += gv[c] * M1w[c * 128 + t];
    h1s[t] = acc;
    __syncthreads();
    if (t < 64) {
        acc = M2b[t];
#pragma unroll 8
        for (int c = 0; c < 128; c++) acc += h1s[c] * M2w[c * 64 + t];
        h2s[t] = acc;
    }
    __syncthreads();
    if (t < 32) {
        acc = M3b[t];
#pragma unroll 8
        for (int c = 0; c < 64; c++) acc += h2s[c] * M3w[c * 32 + t];
        h3s[t] = acc;
    }
    __syncthreads();
    if (t < 32) {
        float v = h3s[t] * M4w[t];
#pragma unroll
        for (int off = 16; off > 0; off >>= 1)
            v += __shfl_down_sync(0xffffffff, v, off);
        if (t == 0) out[g] = v + M4b[0];
    }
}

// ---------------- launch (R3/R6/R7 topology) ----------------
extern "C" void kernel_launch(void* const* d_in, const int* in_sizes, int n_in,
                              void* d_out, int out_size) {
    const int*   ei1  = (const int*)d_in[0];
    const float* ew1  = (const float*)d_in[1];
    const int*   ei2  = (const int*)d_in[2];
    const float* ew2  = (const float*)d_in[3];
    const float* fm0  = (const float*)d_in[4];
    const float* fm1  = (const float*)d_in[5];
    const int*   batch = (const int*)d_in[6];
    const float* W1  = (const float*)d_in[7];
    const float* b1  = (const float*)d_in[8];
    const float* W2  = (const float*)d_in[9];
    const float* b2  = (const float*)d_in[10];
    const float* M1w = (const float*)d_in[11];
    const float* M1b = (const float*)d_in[12];
    const float* M2w = (const float*)d_in[13];
    const float* M2b = (const float*)d_in[14];
    const float* M3w = (const float*)d_in[15];
    const float* M3b = (const float*)d_in[16];
    const float* M4w = (const float*)d_in[17];
    const float* M4b = (const float*)d_in[18];
    float* out = (float*)d_out;

    void *p_h1, *p_h2, *p_x11, *p_x12;
    void *p_rp1, *p_rp2, *p_m1, *p_m2, *p_dis1, *p_dis2;
    cudaGetSymbolAddress(&p_h1, g_h1);
    cudaGetSymbolAddress(&p_h2, g_h2);
    cudaGetSymbolAddress(&p_x11, g_x11);
    cudaGetSymbolAddress(&p_x12, g_x12);
    cudaGetSymbolAddress(&p_rp1, g_rp1);
    cudaGetSymbolAddress(&p_rp2, g_rp2);
    cudaGetSymbolAddress(&p_m1, g_m1);
    cudaGetSymbolAddress(&p_m2, g_m2);
    cudaGetSymbolAddress(&p_dis1, g_dis1);
    cudaGetSymbolAddress(&p_dis2, g_dis2);
    __half* h1 = (__half*)p_h1;  __half* h2 = (__half*)p_h2;
    float* x11 = (float*)p_x11;  float* x12 = (float*)p_x12;

    static cudaStream_t sA = nullptr, sB = nullptr;
    static cudaEvent_t eF = nullptr, eCSR = nullptr, eA = nullptr, eB = nullptr;
    if (sA == nullptr) {
        cudaStreamCreateWithFlags(&sA, cudaStreamNonBlocking);
        cudaStreamCreateWithFlags(&sB, cudaStreamNonBlocking);
        cudaEventCreateWithFlags(&eF, cudaEventDisableTiming);
        cudaEventCreateWithFlags(&eCSR, cudaEventDisableTiming);
        cudaEventCreateWithFlags(&eA, cudaEventDisableTiming);
        cudaEventCreateWithFlags(&eB, cudaEventDisableTiming);
    }

    const int TPB = 256;
    int nodeBlocks = (N_NODES + TPB - 1) / TPB;
    int edgeBlocks = (2 * E_EDGES + TPB - 1) / TPB;
    int gemmBlocks = (N_NODES + 127) / 128;
    int aggBlocks  = (N_NODES * 32 + TPB - 1) / TPB;

    // fork: per-graph gemm1 chains run concurrently with CSR build
    cudaEventRecord(eF, 0);
    cudaStreamWaitEvent(sA, eF, 0);
    cudaStreamWaitEvent(sB, eF, 0);
    k_gemm_tc<<<gemmBlocks, TPB, 0, sA>>>(fm0, W1, h1);
    k_gemm_tc<<<gemmBlocks, TPB, 0, sB>>>(fm1, W1, h2);

    // CSR build chain on default stream (completes before any agg starts)
    k_init<<<nodeBlocks, TPB>>>();
    k_deg<<<edgeBlocks, TPB>>>(ei1, ew1, ei2, ew2);
    k_scan<<<2, 1024>>>();
    k_fill<<<edgeBlocks, TPB>>>(ei1, ew1, ei2, ew2);
    cudaEventRecord(eCSR, 0);
    cudaStreamWaitEvent(sA, eCSR, 0);
    cudaStreamWaitEvent(sB, eCSR, 0);

    // per-graph: agg1 then gemm2
    k_agg1g<<<aggBlocks, TPB, 0, sA>>>(h1, x11, b1, (const int*)p_rp1,
                                       (const int2*)p_m1, (const float*)p_dis1);
    k_gemm_tc<<<gemmBlocks, TPB, 0, sA>>>(x11, W2, h1);
    k_agg1g<<<aggBlocks, TPB, 0, sB>>>(h2, x12, b1, (const int*)p_rp2,
                                       (const int2*)p_m2, (const float*)p_dis2);
    k_gemm_tc<<<gemmBlocks, TPB, 0, sB>>>(x12, W2, h2);

    cudaEventRecord(eA, sA);
    cudaEventRecord(eB, sB);
    cudaStreamWaitEvent(0, eA, 0);
    cudaStreamWaitEvent(0, eB, 0);

    // join: layer-2 aggregation fused with pooling, then MLP
    k_agg2<<<aggBlocks, TPB>>>(h1, h2, b2, batch);
    k_mlp<<<NGRAPH, 128>>>(M1w, M1b, M2w, M2b, M3w, M3b, M4w, M4b, out);
}